// round 16
// baseline (speedup 1.0000x reference)
#include <cuda_runtime.h>
#include <cstdint>

#define IN_CH  128
#define K_HOPS 3
#define MAX_N  10240
#define MAX_E  330000

#define TN     80          // nodes per GEMM block -> 125 blocks (single wave)

// Persistent kernel geometry: 296 blocks x 256 thr = 2 CTAs/SM guaranteed
// resident (launch_bounds), so software grid-sync cannot deadlock.
#define GRID1  296
#define THR1   256
#define GT1    (GRID1 * THR1)
#define NW1    (GRID1 * 8)
#define CHUNK  35          // GRID1*CHUNK = 10360 >= MAX_N+1

// Scratch (__device__ globals: allocation-guard-safe)
__device__ float  g_agg[(size_t)MAX_N * K_HOPS * IN_CH];   // [n][k][c] 15.7 MB
__device__ float4 g_packed[MAX_E];      // {x0,x1,x2, bits(dst)} sorted by src
__device__ int    g_rank[MAX_E];
__device__ int    g_cnt[MAX_N + 1];
__device__ int    g_off[MAX_N + 1];
__device__ int    g_is64;
__device__ int    g_sync[8];            // zero-init; self-resetting (see grid_sync)
__device__ int    g_bsum[GRID1];
__device__ int    g_bbase[GRID1];

// ---------------------------------------------------------------------------
// f32x2 packed helpers (PTX ISA 8.6, sm_100+) and cp.async helpers (Ampere+)
// ---------------------------------------------------------------------------
__device__ __forceinline__ void ffma2(uint64_t& c, uint64_t a, uint64_t b) {
    asm("fma.rn.f32x2 %0, %1, %2, %0;" : "+l"(c) : "l"(a), "l"(b));
}
__device__ __forceinline__ uint64_t bcast2(float v) {
    uint64_t r;
    asm("mov.b64 %0, {%1, %1};" : "=l"(r) : "r"(__float_as_uint(v)));
    return r;
}
__device__ __forceinline__ uint32_t smem_u32(const void* p) {
    uint32_t a;
    asm("{ .reg .u64 t; cvta.to.shared.u64 t, %1; cvt.u32.u64 %0, t; }"
        : "=r"(a) : "l"(p));
    return a;
}
__device__ __forceinline__ void cp_async16(uint32_t dst, const void* src) {
    asm volatile("cp.async.ca.shared.global [%0], [%1], 16;"
                 :: "r"(dst), "l"(src) : "memory");
}
#define CP_COMMIT()  asm volatile("cp.async.commit_group;" ::: "memory")
#define CP_WAIT(n)   asm volatile("cp.async.wait_group %0;" :: "n"(n) : "memory")

// ---------------------------------------------------------------------------
// Software grid sync.  Arrival counter per sync point; block 0 resets counter
// p-1 only AFTER passing sync p (all blocks have then passed p-1, so nobody
// can still be spinning on it).  g_sync[5] (the last) is reset at kernel
// entry by block 0 — safe because no block can reach sync 5 before block 0
// has passed syncs 0..4 (which orders the entry reset first).
// Post-sync __threadfence() is gpu-scope -> flushes/invalidates L1 so the
// next phase reads other SMs' writes.
// ---------------------------------------------------------------------------
__device__ __forceinline__ void grid_sync(int p) {
    __syncthreads();
    if (threadIdx.x == 0) {
        __threadfence();                       // publish this block's writes
        atomicAdd(&g_sync[p], 1);
        while (atomicAdd(&g_sync[p], 0) < GRID1) __nanosleep(64);
        if (blockIdx.x == 0 && p > 0) g_sync[p - 1] = 0;
    }
    __syncthreads();
    __threadfence();                           // acquire: invalidate stale L1
}

// Block-wide exclusive scan over 256 ints; also returns block total.
__device__ __forceinline__ int block_excl_scan(int val, int* s_w, int* tot) {
    int lane = threadIdx.x & 31, w = threadIdx.x >> 5;
    int inc = val;
    #pragma unroll
    for (int d = 1; d < 32; d <<= 1) {
        int u = __shfl_up_sync(0xFFFFFFFFu, inc, d);
        if (lane >= d) inc += u;
    }
    if (lane == 31) s_w[w] = inc;
    __syncthreads();
    if (w == 0) {
        int v = (lane < 8) ? s_w[lane] : 0;
        int wi = v;
        #pragma unroll
        for (int d = 1; d < 8; d <<= 1) {
            int u = __shfl_up_sync(0xFFFFFFFFu, wi, d);
            if (lane >= d) wi += u;
        }
        if (lane < 8) s_w[lane] = wi - v;   // exclusive warp base
        if (lane == 7) s_w[8] = wi;         // block total
    }
    __syncthreads();
    *tot = s_w[8];
    return s_w[w] + inc - val;
}

// ---------------------------------------------------------------------------
// Kernel 1 (persistent): init + count + 3-phase scan + permute + gather.
// ---------------------------------------------------------------------------
__global__ __launch_bounds__(THR1, 2) void mega_kernel(
    const void*  __restrict__ ei,
    const float* __restrict__ X,
    const float* __restrict__ h,
    int E, int N)
{
    __shared__ int s_w[9];
    const int tid = threadIdx.x;
    const int gt  = blockIdx.x * THR1 + tid;

    // ---- P0: zero counters + dtype detect (JAX may emit int32 edge_index) ----
    for (int i = gt; i <= N; i += GT1) g_cnt[i] = 0;
    if (blockIdx.x == 0 && tid == 0) {
        g_sync[5] = 0;                         // entry reset of last counter
        const long long* p64 = (const long long*)ei;
        int ok = 1, c = (E < 64) ? E : 64;
        for (int j = 0; j < c; j++) {
            long long v = p64[j];
            if (v < 0 || v >= (long long)N) { ok = 0; break; }
        }
        g_is64 = ok;
    }
    grid_sync(0);

    // ---- P1: histogram + per-edge rank ----
    const int is64 = g_is64;
    for (int e = gt; e < E; e += GT1) {
        int src = is64 ? (int)__ldg((const long long*)ei + e)
                       : __ldg((const int*)ei + e);
        if ((unsigned)src < (unsigned)N)
            g_rank[e] = atomicAdd(&g_cnt[src], 1);
    }
    grid_sync(1);

    // ---- P2a: per-block local exclusive scan of its CHUNK counters ----
    {
        int idx  = blockIdx.x * CHUNK + tid;
        int have = (tid < CHUNK && idx <= N);
        int val  = have ? g_cnt[idx] : 0;
        int tot;
        int ex = block_excl_scan(val, s_w, &tot);
        if (have) g_off[idx] = ex;
        if (tid == 0) g_bsum[blockIdx.x] = tot;
    }
    grid_sync(2);

    // ---- P2b: block 0 scans the 296 block sums (2 values/thread) ----
    if (blockIdx.x == 0) {
        int v0 = (2 * tid     < GRID1) ? g_bsum[2 * tid]     : 0;
        int v1 = (2 * tid + 1 < GRID1) ? g_bsum[2 * tid + 1] : 0;
        int tot;
        int ex = block_excl_scan(v0 + v1, s_w, &tot);
        if (2 * tid     < GRID1) g_bbase[2 * tid]     = ex;
        if (2 * tid + 1 < GRID1) g_bbase[2 * tid + 1] = ex + v0;
    }
    grid_sync(3);

    // ---- P2c: add block base to local offsets ----
    {
        int bb  = g_bbase[blockIdx.x];
        int idx = blockIdx.x * CHUNK + tid;
        if (tid < CHUNK && idx <= N) g_off[idx] += bb;
    }
    grid_sync(4);

    // ---- P3: permute edges into src-sorted packed records (atomic-free) ----
    for (int e = gt; e < E; e += GT1) {
        int src, dst;
        if (is64) {
            const long long* p = (const long long*)ei;
            src = (int)__ldg(p + e);
            dst = (int)__ldg(p + (size_t)E + e);
        } else {
            const int* p = (const int*)ei;
            src = __ldg(p + e);
            dst = __ldg(p + (size_t)E + e);
        }
        if ((unsigned)src >= (unsigned)N || (unsigned)dst >= (unsigned)N) continue;
        float x0 = __ldg(X + (size_t)e * 3 + 0);
        float x1 = __ldg(X + (size_t)e * 3 + 1);
        float x2 = __ldg(X + (size_t)e * 3 + 2);
        int pos = g_off[src] + g_rank[e];
        g_packed[pos] = make_float4(x0, x1, x2, __int_as_float(dst));
    }
    grid_sync(5);

    // ---- P4: gather-aggregate; warp per node, 4-edge unroll; grid-stride ----
    {
        const int lane = tid & 31;
        for (int n = blockIdx.x * 8 + (tid >> 5); n < N; n += NW1) {
            int beg = __ldg(&g_off[n]);
            int end = __ldg(&g_off[n + 1]);

            float4 a0 = make_float4(0.f, 0.f, 0.f, 0.f);
            float4 a1 = a0, a2 = a0;

            int e = beg;
            for (; e + 3 < end; e += 4) {
                float4 p[4];
                #pragma unroll
                for (int j = 0; j < 4; j++) p[j] = __ldg(&g_packed[e + j]);
                float4 hv[4];
                #pragma unroll
                for (int j = 0; j < 4; j++) {
                    int d = __float_as_int(p[j].w);
                    hv[j] = __ldg(reinterpret_cast<const float4*>(h + (size_t)d * IN_CH) + lane);
                }
                #pragma unroll
                for (int j = 0; j < 4; j++) {
                    a0.x += p[j].x*hv[j].x; a0.y += p[j].x*hv[j].y; a0.z += p[j].x*hv[j].z; a0.w += p[j].x*hv[j].w;
                    a1.x += p[j].y*hv[j].x; a1.y += p[j].y*hv[j].y; a1.z += p[j].y*hv[j].z; a1.w += p[j].y*hv[j].w;
                    a2.x += p[j].z*hv[j].x; a2.y += p[j].z*hv[j].y; a2.z += p[j].z*hv[j].z; a2.w += p[j].z*hv[j].w;
                }
            }
            for (; e < end; e++) {
                float4 p0 = __ldg(&g_packed[e]);
                int d0 = __float_as_int(p0.w);
                float4 h0 = __ldg(reinterpret_cast<const float4*>(h + (size_t)d0 * IN_CH) + lane);
                a0.x += p0.x*h0.x; a0.y += p0.x*h0.y; a0.z += p0.x*h0.z; a0.w += p0.x*h0.w;
                a1.x += p0.y*h0.x; a1.y += p0.y*h0.y; a1.z += p0.y*h0.z; a1.w += p0.y*h0.w;
                a2.x += p0.z*h0.x; a2.y += p0.z*h0.y; a2.z += p0.z*h0.z; a2.w += p0.z*h0.w;
            }

            float4* base = reinterpret_cast<float4*>(g_agg + (size_t)n * (K_HOPS * IN_CH));
            base[lane]      = a0;
            base[32 + lane] = a1;
            base[64 + lane] = a2;
        }
    }
}

// ---------------------------------------------------------------------------
// Kernel 2: GEMM + max + bias (R15 version: f32x2 FMA, async swizzled sA,
// double-buffered sW).  Smem 208 KB, 125 blocks, single wave.
// ---------------------------------------------------------------------------
#define OFF_AT  0
#define OFF_NAT (IN_CH * TN)
#define OFF_W   (2 * IN_CH * TN)
#define GEMM_SMEM_F (2 * IN_CH * TN + 2 * IN_CH * IN_CH)   // 53248 floats

__global__ __launch_bounds__(256, 1) void gemm_max_bias_kernel(
    const float* __restrict__ W,     // [3][128][128]
    const float* __restrict__ bias,  // [128]
    float* __restrict__ out,         // [N][128]
    int N)
{
    extern __shared__ float smem[];
    float* sAT  = smem + OFF_AT;
    float* sAn  = smem + OFF_NAT;
    float* sWb  = smem + OFF_W;

    const int tid = threadIdx.x;
    const int to  = tid & 31;
    const int tw  = tid >> 5;
    const int n0  = blockIdx.x * TN;

    const uint32_t aNatBase = smem_u32(sAn);
    const uint32_t wBase    = smem_u32(sWb);

    auto issue_sA = [&](int k) {
        #pragma unroll
        for (int r = 0; r < 10; r++) {
            int idx = tid + r * 256;
            int nn  = idx >> 5;
            int p   = idx & 31;
            int sl  = p ^ (nn & 7);
            const float* src = g_agg + (size_t)(n0 + nn) * (K_HOPS * IN_CH)
                             + k * IN_CH + sl * 4;
            cp_async16(aNatBase + (uint32_t)idx * 16u, src);
        }
    };
    auto issue_sW = [&](int k, int buf) {
        uint32_t dst = wBase + (uint32_t)buf * IN_CH * IN_CH * 4u;
        const float4* src = reinterpret_cast<const float4*>(
            W + (size_t)k * IN_CH * IN_CH);
        #pragma unroll
        for (int r = 0; r < 16; r++)
            cp_async16(dst + (tid + r * 256) * 16, src + tid + r * 256);
    };

    issue_sA(0); issue_sW(0, 0); CP_COMMIT();
    issue_sW(1, 1); CP_COMMIT();

    float M[10][4];
    #pragma unroll
    for (int j = 0; j < 10; j++)
        #pragma unroll
        for (int q = 0; q < 4; q++) M[j][q] = -3.0e38f;

    for (int k = 0; k < K_HOPS; k++) {
        if (k == 0) { CP_WAIT(1); } else { CP_WAIT(0); }
        __syncthreads();

        #pragma unroll
        for (int r = 0; r < 10; r++) {
            int idx = tid + r * 256;
            int nn  = idx % TN;
            int sl  = idx / TN;
            float4 v = *reinterpret_cast<const float4*>(
                sAn + nn * IN_CH + (sl ^ (nn & 7)) * 4);
            sAT[(sl * 4 + 0) * TN + nn] = v.x;
            sAT[(sl * 4 + 1) * TN + nn] = v.y;
            sAT[(sl * 4 + 2) * TN + nn] = v.z;
            sAT[(sl * 4 + 3) * TN + nn] = v.w;
        }
        __syncthreads();

        if (k == 0)      { issue_sA(1); CP_COMMIT(); }
        else if (k == 1) { issue_sA(2); issue_sW(2, 0); CP_COMMIT(); }

        const float* sW = sWb + (size_t)(k & 1) * IN_CH * IN_CH;

        uint64_t C[5][4];
        #pragma unroll
        for (int p = 0; p < 5; p++)
            #pragma unroll
            for (int q = 0; q < 4; q++) C[p][q] = 0ull;

        const float* aRow0 = sAT + tw * 10;
        #pragma unroll 8
        for (int i = 0; i < IN_CH; i++) {
            const uint64_t* ap = reinterpret_cast<const uint64_t*>(aRow0 + i * TN);
            uint64_t a0 = ap[0], a1 = ap[1], a2 = ap[2], a3 = ap[3], a4 = ap[4];
            float4 b = *reinterpret_cast<const float4*>(&sW[i * IN_CH + to * 4]);
            uint64_t b0 = bcast2(b.x), b1 = bcast2(b.y), b2 = bcast2(b.z), b3 = bcast2(b.w);
            ffma2(C[0][0], a0, b0); ffma2(C[0][1], a0, b1); ffma2(C[0][2], a0, b2); ffma2(C[0][3], a0, b3);
            ffma2(C[1][0], a1, b0); ffma2(C[1][1], a1, b1); ffma2(C[1][2], a1, b2); ffma2(C[1][3], a1, b3);
            ffma2(C[2][0], a2, b0); ffma2(C[2][1], a2, b1); ffma2(C[2][2], a2, b2); ffma2(C[2][3], a2, b3);
            ffma2(C[3][0], a3, b0); ffma2(C[3][1], a3, b1); ffma2(C[3][2], a3, b2); ffma2(C[3][3], a3, b3);
            ffma2(C[4][0], a4, b0); ffma2(C[4][1], a4, b1); ffma2(C[4][2], a4, b2); ffma2(C[4][3], a4, b3);
        }

        #pragma unroll
        for (int p = 0; p < 5; p++)
            #pragma unroll
            for (int q = 0; q < 4; q++) {
                float lo = __uint_as_float((uint32_t)(C[p][q] & 0xFFFFFFFFull));
                float hi = __uint_as_float((uint32_t)(C[p][q] >> 32));
                M[2 * p][q]     = fmaxf(M[2 * p][q], lo);
                M[2 * p + 1][q] = fmaxf(M[2 * p + 1][q], hi);
            }
    }

    float4 bv = __ldg(reinterpret_cast<const float4*>(bias) + to);
    #pragma unroll
    for (int j = 0; j < 10; j++) {
        int node = n0 + tw * 10 + j;
        if (node < N) {
            float4 o;
            o.x = M[j][0] + bv.x;
            o.y = M[j][1] + bv.y;
            o.z = M[j][2] + bv.z;
            o.w = M[j][3] + bv.w;
            reinterpret_cast<float4*>(out + (size_t)node * IN_CH)[to] = o;
        }
    }
}

// ---------------------------------------------------------------------------
// Launch.  Inputs (metadata order): h[f32 N*128], X[f32 E*3],
// edge_index[2*E, int32 OR int64], batch_node[f32 N] (unused),
// weight[f32 3*128*128], bias[f32 128].  Output: f32 [N][128].
// ---------------------------------------------------------------------------
extern "C" void kernel_launch(void* const* d_in, const int* in_sizes, int n_in,
                              void* d_out, int out_size) {
    const float* h    = (const float*)d_in[0];
    const float* X    = (const float*)d_in[1];
    const void*  ei   = d_in[2];
    const float* W    = (const float*)d_in[4];
    const float* bias = (const float*)d_in[5];
    float*       out  = (float*)d_out;

    int N = in_sizes[0] / IN_CH;
    int E = in_sizes[1] / K_HOPS;

    const int SMEM_BYTES = GEMM_SMEM_F * (int)sizeof(float);   // 212992
    static int smem_set = 0;
    if (!smem_set) {
        cudaFuncSetAttribute(gemm_max_bias_kernel,
                             cudaFuncAttributeMaxDynamicSharedMemorySize, SMEM_BYTES);
        smem_set = 1;
    }

    mega_kernel<<<GRID1, THR1>>>(ei, X, h, E, N);
    gemm_max_bias_kernel<<<(N + TN - 1) / TN, 256, SMEM_BYTES>>>(W, bias, out, N);
}